// round 4
// baseline (speedup 1.0000x reference)
#include <cuda_runtime.h>
#include <cstdint>

// out[n] = S * ( sum_k (x[k]-X_ZP) * y[k,n]  -  Y_ZP * sum_k (x[k]-X_ZP) )
// Exact int32 accumulation. X_SCALE=0.0215, X_ZP=-25, Y_SCALE=0.0176, Y_ZP=18
//
// Single fused kernel: grid (16 n-tiles x 64 K-splits) x 256 threads.
// Each block streams a 128-row x 1024-col tile of y (coalesced int4, __ldcs)
// and stores int32 partials. The LAST block to finish each n-tile (per-tile
// ticket counter) reduces the 64 partials (L2-hit) + computes the zero-point
// correction from x, and writes the fp32 output. Tickets self-reset for
// graph replay.

#define KDIM 8192
#define NDIM 16384
#define THREADS 256
#define COLS_PER_THREAD 4
#define COLS_PER_BLOCK (THREADS * COLS_PER_THREAD)    // 1024
#define N_TILES (NDIM / COLS_PER_BLOCK)               // 16
#define KCHUNK 128
#define SPLITS (KDIM / KCHUNK)                        // 64

__device__ int g_part[SPLITS][NDIM];        // per-split partial dot products
__device__ unsigned g_tickets[N_TILES];     // zero-init at load; reset each run

__global__ __launch_bounds__(THREADS) void gemv_fused_kernel(
    const int* __restrict__ x, const int* __restrict__ y,
    float* __restrict__ out)
{
    __shared__ int sa[KCHUNK];
    __shared__ bool s_last;
    __shared__ int s_warp[THREADS / 32];

    const int tid   = threadIdx.x;
    const int tile  = blockIdx.x;
    const int split = blockIdx.y;
    const int k0    = split * KCHUNK;

    // a[k] = x[k] - X_ZP = x[k] + 25
    if (tid < KCHUNK)
        sa[tid] = x[k0 + tid] + 25;
    __syncthreads();

    const int n0 = tile * COLS_PER_BLOCK + tid * COLS_PER_THREAD;
    const int4* yp = reinterpret_cast<const int4*>(y + (size_t)k0 * NDIM + n0);
    const size_t strideV = NDIM / 4;

    int a0 = 0, a1 = 0, a2 = 0, a3 = 0;
    #pragma unroll 8
    for (int kk = 0; kk < KCHUNK; kk++) {
        const int a = sa[kk];
        const int4 v = __ldcs(&yp[(size_t)kk * strideV]);
        a0 += a * v.x;  a1 += a * v.y;  a2 += a * v.z;  a3 += a * v.w;
    }

    *reinterpret_cast<int4*>(&g_part[split][n0]) = make_int4(a0, a1, a2, a3);

    // Make partials visible, then take a ticket for this n-tile.
    __threadfence();
    __syncthreads();
    if (tid == 0) {
        unsigned t = atomicAdd(&g_tickets[tile], 1u);
        s_last = (t == SPLITS - 1);
    }
    __syncthreads();
    if (!s_last) return;

    // ---- Last block for this n-tile: reduce + finalize its 1024 columns ----

    // Zero-point correction: sum_a = sum_k (x[k] + 25), computed redundantly.
    int sx = 0;
    #pragma unroll
    for (int i = 0; i < KDIM / THREADS; i++)
        sx += __ldg(&x[tid + i * THREADS]);
    #pragma unroll
    for (int o = 16; o > 0; o >>= 1)
        sx += __shfl_down_sync(0xffffffffu, sx, o);
    if ((tid & 31) == 0) s_warp[tid >> 5] = sx;
    __syncthreads();
    int sum_a;
    {
        int s = 0;
        #pragma unroll
        for (int w = 0; w < THREADS / 32; w++) s += s_warp[w];
        sum_a = s + 25 * KDIM;
    }

    // Reduce 64 partials per column (int4 per thread = 4 columns).
    int r0 = 0, r1 = 0, r2 = 0, r3 = 0;
    #pragma unroll 8
    for (int s = 0; s < SPLITS; s++) {
        const int4 v = *reinterpret_cast<const int4*>(&g_part[s][n0]);
        r0 += v.x;  r1 += v.y;  r2 += v.z;  r3 += v.w;
    }

    const float S = (float)(0.0215 * 0.0176);
    const int corr = 18 * sum_a;
    float4 o;
    o.x = S * (float)(r0 - corr);
    o.y = S * (float)(r1 - corr);
    o.z = S * (float)(r2 - corr);
    o.w = S * (float)(r3 - corr);
    *reinterpret_cast<float4*>(&out[n0]) = o;

    // Reset ticket for the next graph replay.
    if (tid == 0) g_tickets[tile] = 0;
}

extern "C" void kernel_launch(void* const* d_in, const int* in_sizes, int n_in,
                              void* d_out, int out_size) {
    const int* x = (const int*)d_in[0];   // [K]
    const int* y = (const int*)d_in[1];   // [K, N]
    float* out = (float*)d_out;           // [N]

    dim3 grid(N_TILES, SPLITS);
    gemv_fused_kernel<<<grid, THREADS>>>(x, y, out);
}

// round 5
// speedup vs baseline: 1.0972x; 1.0972x over previous
#include <cuda_runtime.h>
#include <cstdint>

// out[n] = S * ( sum_k (x[k]-X_ZP) * y[k,n]  -  Y_ZP * sum_k (x[k]-X_ZP) )
// Exact int32 accumulation. X_SCALE=0.0215, X_ZP=-25, Y_SCALE=0.0176, Y_ZP=18
//
// gemv:     (16 n-tiles x 64 K-splits) x 256 thr. Coalesced int4 __ldcs
//           stream of y at ~6.8 TB/s; plain STG partials. (Unchanged from
//           R3 — measured 84.5% of HBM spec; do not touch.)
// finalize: 256 blocks x 256 thr; 4 threads per column, 16 splits each
//           (high MLP, coalesced), shared-mem combine.

#define KDIM 8192
#define NDIM 16384
#define THREADS 256
#define COLS_PER_THREAD 4
#define COLS_PER_BLOCK (THREADS * COLS_PER_THREAD)    // 1024
#define N_TILES (NDIM / COLS_PER_BLOCK)               // 16
#define KCHUNK 128
#define SPLITS (KDIM / KCHUNK)                        // 64

#define FIN_THREADS 256
#define FIN_COLS 64                                   // columns per block
#define FIN_QUARTERS 4                                // threads per column
#define FIN_SPLITS_PER_THREAD (SPLITS / FIN_QUARTERS) // 16
#define FIN_BLOCKS (NDIM / FIN_COLS)                  // 256

__device__ int g_part[SPLITS][NDIM];   // per-split partial dot products
__device__ int g_sa_part[SPLITS];      // per-split sum of (x[k]+25)

__global__ __launch_bounds__(THREADS) void gemv_kernel(
    const int* __restrict__ x, const int* __restrict__ y)
{
    __shared__ int sa[KCHUNK];
    const int tid   = threadIdx.x;
    const int split = blockIdx.y;
    const int k0    = split * KCHUNK;

    // a[k] = x[k] - X_ZP = x[k] + 25
    if (tid < KCHUNK)
        sa[tid] = x[k0 + tid] + 25;
    __syncthreads();

    const int n0 = blockIdx.x * COLS_PER_BLOCK + tid * COLS_PER_THREAD;
    const int4* yp = reinterpret_cast<const int4*>(y + (size_t)k0 * NDIM + n0);
    const size_t strideV = NDIM / 4;

    int a0 = 0, a1 = 0, a2 = 0, a3 = 0;
    #pragma unroll 8
    for (int kk = 0; kk < KCHUNK; kk++) {
        const int a = sa[kk];
        const int4 v = __ldcs(&yp[(size_t)kk * strideV]);
        a0 += a * v.x;  a1 += a * v.y;  a2 += a * v.z;  a3 += a * v.w;
    }

    *reinterpret_cast<int4*>(&g_part[split][n0]) = make_int4(a0, a1, a2, a3);

    // one n-tile per split contributes the sum-of-a partial
    if (blockIdx.x == 0 && tid < 32) {
        int s = 0;
        #pragma unroll
        for (int i = 0; i < KCHUNK / 32; i++)
            s += sa[tid + i * 32];
        #pragma unroll
        for (int o = 16; o > 0; o >>= 1)
            s += __shfl_down_sync(0xffffffffu, s, o);
        if (tid == 0) g_sa_part[split] = s;
    }
}

__global__ __launch_bounds__(FIN_THREADS) void finalize_kernel(float* __restrict__ out) {
    __shared__ int s_red[FIN_QUARTERS][FIN_COLS];
    __shared__ int s_sa;

    const int tid  = threadIdx.x;
    const int col  = blockIdx.x * FIN_COLS + (tid & (FIN_COLS - 1));
    const int q    = tid >> 6;                 // 0..3
    const int sbase = q * FIN_SPLITS_PER_THREAD;

    if (tid < 32) {
        int s = g_sa_part[tid] + g_sa_part[tid + 32];
        #pragma unroll
        for (int o = 16; o > 0; o >>= 1)
            s += __shfl_down_sync(0xffffffffu, s, o);
        if (tid == 0) s_sa = s;
    }

    // 16 independent coalesced loads per thread (high MLP).
    int r0 = 0, r1 = 0, r2 = 0, r3 = 0;
    #pragma unroll
    for (int i = 0; i < FIN_SPLITS_PER_THREAD; i += 4) {
        r0 += g_part[sbase + i + 0][col];
        r1 += g_part[sbase + i + 1][col];
        r2 += g_part[sbase + i + 2][col];
        r3 += g_part[sbase + i + 3][col];
    }
    s_red[q][tid & (FIN_COLS - 1)] = (r0 + r1) + (r2 + r3);
    __syncthreads();

    if (tid < FIN_COLS) {
        const int acc = (s_red[0][tid] + s_red[1][tid]) +
                        (s_red[2][tid] + s_red[3][tid]);
        const float S = (float)(0.0215 * 0.0176);
        out[blockIdx.x * FIN_COLS + tid] = S * (float)(acc - 18 * s_sa);
    }
}

extern "C" void kernel_launch(void* const* d_in, const int* in_sizes, int n_in,
                              void* d_out, int out_size) {
    const int* x = (const int*)d_in[0];   // [K]
    const int* y = (const int*)d_in[1];   // [K, N]
    float* out = (float*)d_out;           // [N]

    dim3 grid(N_TILES, SPLITS);
    gemv_kernel<<<grid, THREADS>>>(x, y);
    finalize_kernel<<<FIN_BLOCKS, FIN_THREADS>>>(out);
}